// round 2
// baseline (speedup 1.0000x reference)
#include <cuda_runtime.h>

#define KT 96      // trials
#define DD 256     // embed dim
#define PB 40      // phoneme bins
#define CG 8       // gate hidden

#define KC 64      // d-chunk staged in smem

// Scratch for normalized inputs (allocation-free rule: __device__ globals)
__device__ float g_En[KT * DD * PB];
__device__ float g_Tn[KT * DD * PB];

// ---------------------------------------------------------------------------
// Kernel 1: L2-normalize over d for each (k, p) column.
// grid = 2*KT blocks, 256 threads. Layout kept as [k][d][p].
// ---------------------------------------------------------------------------
__global__ __launch_bounds__(256) void norm_kernel(
    const float* __restrict__ enroll,
    const float* __restrict__ test)
{
    __shared__ float s[DD * PB];      // 40 KB slab
    __shared__ float scale[PB];

    int b = blockIdx.x;
    const float* src = (b < KT) ? enroll : test;
    float*       dst = (b < KT) ? g_En   : g_Tn;
    int k = (b < KT) ? b : (b - KT);

    const float4* src4 = (const float4*)(src + (size_t)k * DD * PB);
    float4* s4 = (float4*)s;
    #pragma unroll 4
    for (int i = threadIdx.x; i < DD * PB / 4; i += 256) s4[i] = src4[i];
    __syncthreads();

    if (threadIdx.x < PB) {
        float ss = 0.f;
        #pragma unroll 8
        for (int d = 0; d < DD; d++) {
            float v = s[d * PB + threadIdx.x];
            ss = fmaf(v, v, ss);
        }
        scale[threadIdx.x] = 1.0f / fmaxf(sqrtf(ss), 1e-12f);
    }
    __syncthreads();

    float* out = dst + (size_t)k * DD * PB;
    #pragma unroll 4
    for (int i = threadIdx.x; i < DD * PB; i += 256) {
        out[i] = s[i] * scale[i % PB];
    }
}

// ---------------------------------------------------------------------------
// Gate: g(x) = sum_c fc2[c] * tanh(x * fc1_w[c] + fc1_b[c])
// ---------------------------------------------------------------------------
__device__ __forceinline__ float gate_fn(float x, const float w1[CG],
                                         const float b1[CG], const float w2[CG])
{
    float g = 0.f;
    #pragma unroll
    for (int c = 0; c < CG; c++)
        g = fmaf(w2[c], tanhf(fmaf(x, w1[c], b1[c])), g);
    return g;
}

// ---------------------------------------------------------------------------
// Kernel 2: one block per (k, l) pair. 64 threads, each owns a 5x5 tile of
// the 40x40 pho block. d-loop staged through smem in KC-chunks. Fused
// gate + nonzero-count + two-stage masked-mean epilogue.
// ---------------------------------------------------------------------------
__global__ __launch_bounds__(64) void pair_kernel(
    const float* __restrict__ fc1w,
    const float* __restrict__ fc1b,
    const float* __restrict__ fc2w,
    float* __restrict__ out)
{
    __shared__ float sE[KC][PB];     // 10 KB
    __shared__ float sT[KC][PB];     // 10 KB
    __shared__ float red [PB][9];    // stage-1 partial sums (pad 9 vs bank)
    __shared__ float redc[PB][9];    // stage-1 partial counts
    __shared__ float s2[PB];
    __shared__ float c2[PB];

    const int k = blockIdx.x;
    const int l = blockIdx.y;
    const int tid = threadIdx.x;
    const int ty = tid >> 3;         // 0..7  -> i block of 5
    const int tx = tid & 7;          // 0..7  -> j block of 5

    float acc[5][5];
    #pragma unroll
    for (int a = 0; a < 5; a++)
        #pragma unroll
        for (int b = 0; b < 5; b++) acc[a][b] = 0.f;

    const float4* Ebase = (const float4*)(g_En + (size_t)k * DD * PB);
    const float4* Tbase = (const float4*)(g_Tn + (size_t)l * DD * PB);
    float4* sE4 = (float4*)&sE[0][0];
    float4* sT4 = (float4*)&sT[0][0];

    for (int d0 = 0; d0 < DD; d0 += KC) {
        // Stage KC*PB = 2560 floats per tile: contiguous copy, 640 float4 each.
        const int base4 = d0 * PB / 4;
        #pragma unroll
        for (int i = 0; i < KC * PB / 4 / 64; i++) {
            int idx = tid + i * 64;
            sE4[idx] = Ebase[base4 + idx];
            sT4[idx] = Tbase[base4 + idx];
        }
        __syncthreads();

        #pragma unroll 4
        for (int dd = 0; dd < KC; dd++) {
            float a[5], b[5];
            #pragma unroll
            for (int m = 0; m < 5; m++) {
                a[m] = sE[dd][ty * 5 + m];
                b[m] = sT[dd][tx * 5 + m];
            }
            #pragma unroll
            for (int mi = 0; mi < 5; mi++)
                #pragma unroll
                for (int mj = 0; mj < 5; mj++)
                    acc[mi][mj] = fmaf(a[mi], b[mj], acc[mi][mj]);
        }
        __syncthreads();
    }

    // Gate parameters into registers (small, L1-resident)
    float w1[CG], b1[CG], w2[CG];
    #pragma unroll
    for (int c = 0; c < CG; c++) {
        w1[c] = fc1w[c];
        b1[c] = fc1b[c];
        w2[c] = fc2w[c];
    }

    // Stage 1: per-i partial (over this thread's 5 j's) of gate(x)*x and nnz
    #pragma unroll
    for (int mi = 0; mi < 5; mi++) {
        float s = 0.f, cnt = 0.f;
        #pragma unroll
        for (int mj = 0; mj < 5; mj++) {
            float x = acc[mi][mj];
            cnt += (x != 0.0f) ? 1.0f : 0.0f;
            s = fmaf(gate_fn(x, w1, b1, w2), x, s);
        }
        red [ty * 5 + mi][tx] = s;
        redc[ty * 5 + mi][tx] = cnt;
    }
    __syncthreads();

    // Finalize stage 1 per i-row; apply gate again for stage 2 term
    if (tid < PB) {
        float s = 0.f, c = 0.f;
        #pragma unroll
        for (int x = 0; x < 8; x++) { s += red[tid][x]; c += redc[tid][x]; }
        float v = s / (c + 1e-6f);
        s2[tid] = gate_fn(v, w1, b1, w2) * v;
        c2[tid] = (v != 0.0f) ? 1.0f : 0.0f;
    }
    __syncthreads();

    if (tid == 0) {
        float s = 0.f, c = 0.f;
        #pragma unroll
        for (int i = 0; i < PB; i++) { s += s2[i]; c += c2[i]; }
        out[k * KT + l] = s / (c + 1e-6f);
    }
}

// ---------------------------------------------------------------------------
extern "C" void kernel_launch(void* const* d_in, const int* in_sizes, int n_in,
                              void* d_out, int out_size)
{
    const float* enroll = (const float*)d_in[0];
    const float* test   = (const float*)d_in[1];
    const float* fc1w   = (const float*)d_in[2];
    const float* fc1b   = (const float*)d_in[3];
    const float* fc2w   = (const float*)d_in[4];
    float* out = (float*)d_out;

    norm_kernel<<<2 * KT, 256>>>(enroll, test);

    dim3 grid(KT, KT);
    pair_kernel<<<grid, 64>>>(fc1w, fc1b, fc2w, out);
}

// round 3
// speedup vs baseline: 1.4376x; 1.4376x over previous
#include <cuda_runtime.h>

#define KT 96      // trials
#define DD 256     // embed dim
#define PB 40      // phoneme bins
#define CG 8       // gate hidden

#define KC 64      // d-chunk staged in smem
#define KCP (KC + 4)   // padded row stride (floats) -> bank-conflict-free

// Normalized inputs, stored TRANSPOSED: [k][p][d]
__device__ float g_En[KT * PB * DD];
__device__ float g_Tn[KT * PB * DD];

// ---------------------------------------------------------------------------
// Kernel 1: L2-normalize over d for each (k, p), write transposed [k][p][d].
// grid = 2*KT blocks, 256 threads.
// ---------------------------------------------------------------------------
__global__ __launch_bounds__(256) void norm_kernel(
    const float* __restrict__ enroll,
    const float* __restrict__ test)
{
    __shared__ float s[DD * (PB + 1)];   // padded rows: s[d*41 + p]
    __shared__ float scale[PB];

    int b = blockIdx.x;
    const float* src = (b < KT) ? enroll : test;
    float*       dst = (b < KT) ? g_En   : g_Tn;
    int k = (b < KT) ? b : (b - KT);

    const float* in = src + (size_t)k * DD * PB;
    #pragma unroll 4
    for (int i = threadIdx.x; i < DD * PB; i += 256) {
        int d = i / PB, p = i - d * PB;
        s[d * (PB + 1) + p] = in[i];
    }
    __syncthreads();

    if (threadIdx.x < PB) {
        float ss = 0.f;
        #pragma unroll 8
        for (int d = 0; d < DD; d++) {
            float v = s[d * (PB + 1) + threadIdx.x];
            ss = fmaf(v, v, ss);
        }
        scale[threadIdx.x] = 1.0f / fmaxf(sqrtf(ss), 1e-12f);
    }
    __syncthreads();

    float* out = dst + (size_t)k * PB * DD;
    #pragma unroll 4
    for (int i = threadIdx.x; i < PB * DD; i += 256) {
        int p = i >> 8, d = i & 255;            // i = p*DD + d
        out[i] = s[d * (PB + 1) + p] * scale[p];
    }
}

// ---------------------------------------------------------------------------
// Packed fp32x2 FMA (Blackwell): 2 MACs per FMA-pipe slot.
// ---------------------------------------------------------------------------
#define FMA2(acc, av, bv) \
    asm("fma.rn.f32x2 %0, %1, %2, %0;" : "+l"(acc) : "l"(av), "l"(bv))

__device__ __forceinline__ float tanh_fast(float x) {
    float y;
    asm("tanh.approx.f32 %0, %1;" : "=f"(y) : "f"(x));
    return y;
}

// Gate: g(x) = sum_c fc2[c] * tanh(x * fc1_w[c] + fc1_b[c])
__device__ __forceinline__ float gate_fn(float x, const float w1[CG],
                                         const float b1[CG], const float w2[CG])
{
    float g = 0.f;
    #pragma unroll
    for (int c = 0; c < CG; c++)
        g = fmaf(w2[c], tanh_fast(fmaf(x, w1[c], b1[c])), g);
    return g;
}

// ---------------------------------------------------------------------------
// Kernel 2: one block per (k, l) pair. 64 threads, each owns a 5x5 tile of
// the 40x40 pho block. Transposed smem staging ([p][d]) so the d-loop loads
// LDS.128 and accumulates with packed f32x2 FMAs (lanes = even/odd d).
// ---------------------------------------------------------------------------
__global__ __launch_bounds__(64) void pair_kernel(
    const float* __restrict__ fc1w,
    const float* __restrict__ fc1b,
    const float* __restrict__ fc2w,
    float* __restrict__ out)
{
    __shared__ float sE[PB][KCP];    // ~10.9 KB
    __shared__ float sT[PB][KCP];    // ~10.9 KB
    __shared__ float red [PB][9];
    __shared__ float redc[PB][9];
    __shared__ float s2[PB];
    __shared__ float c2[PB];

    const int k = blockIdx.x;
    const int l = blockIdx.y;
    const int tid = threadIdx.x;
    const int ty = tid >> 3;         // 0..7 -> i block of 5
    const int tx = tid & 7;          // 0..7 -> j block of 5

    unsigned long long acc[5][5];    // packed (even-d, odd-d) partial sums
    #pragma unroll
    for (int a = 0; a < 5; a++)
        #pragma unroll
        for (int b = 0; b < 5; b++) acc[a][b] = 0ull;

    const float* Eb = g_En + (size_t)k * PB * DD;
    const float* Tb = g_Tn + (size_t)l * PB * DD;

    for (int d0 = 0; d0 < DD; d0 += KC) {
        // Stage: 40 rows x 16 float4 per buffer (2560 floats each).
        #pragma unroll
        for (int it = 0; it < (PB * (KC / 4)) / 64; it++) {
            int i = tid + it * 64;
            int p = i >> 4, q = i & 15;
            ((float4*)&sE[p][0])[q] =
                ((const float4*)(Eb + (size_t)p * DD + d0))[q];
            ((float4*)&sT[p][0])[q] =
                ((const float4*)(Tb + (size_t)p * DD + d0))[q];
        }
        __syncthreads();

        #pragma unroll 4
        for (int dd = 0; dd < KC; dd += 4) {
            ulonglong2 a[5], b[5];
            #pragma unroll
            for (int m = 0; m < 5; m++) {
                a[m] = *(const ulonglong2*)&sE[ty * 5 + m][dd];
                b[m] = *(const ulonglong2*)&sT[tx * 5 + m][dd];
            }
            #pragma unroll
            for (int mi = 0; mi < 5; mi++)
                #pragma unroll
                for (int mj = 0; mj < 5; mj++) {
                    FMA2(acc[mi][mj], a[mi].x, b[mj].x);
                    FMA2(acc[mi][mj], a[mi].y, b[mj].y);
                }
        }
        __syncthreads();
    }

    // Gate parameters into registers
    float w1[CG], b1[CG], w2[CG];
    #pragma unroll
    for (int c = 0; c < CG; c++) {
        w1[c] = fc1w[c];
        b1[c] = fc1b[c];
        w2[c] = fc2w[c];
    }

    // Stage 1: per-i partial (this thread's 5 j's) of gate(x)*x and nnz count
    #pragma unroll
    for (int mi = 0; mi < 5; mi++) {
        float s = 0.f, cnt = 0.f;
        #pragma unroll
        for (int mj = 0; mj < 5; mj++) {
            unsigned long long v = acc[mi][mj];
            float lo = __uint_as_float((unsigned)(v & 0xffffffffu));
            float hi = __uint_as_float((unsigned)(v >> 32));
            float x = lo + hi;
            cnt += (x != 0.0f) ? 1.0f : 0.0f;
            s = fmaf(gate_fn(x, w1, b1, w2), x, s);
        }
        red [ty * 5 + mi][tx] = s;
        redc[ty * 5 + mi][tx] = cnt;
    }
    __syncthreads();

    // Stage 2: finalize per i-row, apply gate again
    if (tid < PB) {
        float s = 0.f, c = 0.f;
        #pragma unroll
        for (int x = 0; x < 8; x++) { s += red[tid][x]; c += redc[tid][x]; }
        float v = s / (c + 1e-6f);
        s2[tid] = gate_fn(v, w1, b1, w2) * v;
        c2[tid] = (v != 0.0f) ? 1.0f : 0.0f;
    }
    __syncthreads();

    if (tid == 0) {
        float s = 0.f, c = 0.f;
        #pragma unroll
        for (int i = 0; i < PB; i++) { s += s2[i]; c += c2[i]; }
        out[k * KT + l] = s / (c + 1e-6f);
    }
}

// ---------------------------------------------------------------------------
extern "C" void kernel_launch(void* const* d_in, const int* in_sizes, int n_in,
                              void* d_out, int out_size)
{
    const float* enroll = (const float*)d_in[0];
    const float* test   = (const float*)d_in[1];
    const float* fc1w   = (const float*)d_in[2];
    const float* fc1b   = (const float*)d_in[3];
    const float* fc2w   = (const float*)d_in[4];
    float* out = (float*)d_out;

    norm_kernel<<<2 * KT, 256>>>(enroll, test);

    dim3 grid(KT, KT);
    pair_kernel<<<grid, 64>>>(fc1w, fc1b, fc2w, out);
}

// round 5
// speedup vs baseline: 3.1703x; 2.2053x over previous
#include <cuda_runtime.h>
#include <cuda_fp16.h>
#include <cstdint>

#define KT 96
#define DD 256
#define PB 40
#define CG 8

#define MTOT 3840          // KT*PB
#define KF   768           // 3-split K
#define TM   128
#define TN   160
#define NCH  12            // K chunks of 64 halves
#define ROWP 72            // padded smem row stride (halves) = 144B
#define NMT  (MTOT / TM)   // 30
#define NNT  (MTOT / TN)   // 24

#define A_BUF_B (TM * ROWP * 2)   // 18432
#define B_BUF_B (TN * ROWP * 2)   // 23040
#define SMEM_BYTES (2 * (A_BUF_B + B_BUF_B))  // 82944

// fp16 split operands, row-major [row][768]
__device__ __align__(16) __half g_A[MTOT * KF];
__device__ __align__(16) __half g_B[MTOT * KF];
// stage-1 result pho1[m][l]
__device__ float g_pho1[MTOT * KT];

// ---------------------------------------------------------------------------
__device__ __forceinline__ uint32_t smem_u32(const void* p) {
    uint32_t a;
    asm("{ .reg .u64 t; cvta.to.shared.u64 t, %1; cvt.u32.u64 %0, t; }"
        : "=r"(a) : "l"(p));
    return a;
}

#define CP_ASYNC16(dst, src) \
    asm volatile("cp.async.cg.shared.global [%0], [%1], 16;" \
                 :: "r"(dst), "l"(src) : "memory")
#define CP_COMMIT() asm volatile("cp.async.commit_group;" ::: "memory")
#define CP_WAIT1()  asm volatile("cp.async.wait_group 1;" ::: "memory")
#define CP_WAIT0()  asm volatile("cp.async.wait_group 0;" ::: "memory")

#define LDSM4(r0, r1, r2, r3, a) \
    asm volatile("ldmatrix.sync.aligned.m8n8.x4.shared.b16 {%0,%1,%2,%3}, [%4];" \
                 : "=r"(r0), "=r"(r1), "=r"(r2), "=r"(r3) : "r"(a))
#define LDSM2(r0, r1, a) \
    asm volatile("ldmatrix.sync.aligned.m8n8.x2.shared.b16 {%0,%1}, [%2];" \
                 : "=r"(r0), "=r"(r1) : "r"(a))

#define MMA16816(c, a0, a1, a2, a3, b0, b1) \
    asm volatile("mma.sync.aligned.m16n8k16.row.col.f32.f16.f16.f32 " \
                 "{%0,%1,%2,%3},{%4,%5,%6,%7},{%8,%9},{%0,%1,%2,%3};" \
                 : "+f"((c)[0]), "+f"((c)[1]), "+f"((c)[2]), "+f"((c)[3]) \
                 : "r"(a0), "r"(a1), "r"(a2), "r"(a3), "r"(b0), "r"(b1))

__device__ __forceinline__ float tanh_fast(float x) {
    float y;
    asm("tanh.approx.f32 %0, %1;" : "=f"(y) : "f"(x));
    return y;
}
__device__ __forceinline__ float gate_fn(float x, const float w1[CG],
                                         const float b1[CG], const float w2[CG]) {
    float g = 0.f;
    #pragma unroll
    for (int c = 0; c < CG; c++)
        g = fmaf(w2[c], tanh_fast(fmaf(x, w1[c], b1[c])), g);
    return g;
}

// ---------------------------------------------------------------------------
// Kernel 1: L2-normalize over d; fp16 3-split into g_A / g_B.
// A row m: [hi | hi | lo] ; B row n: [hi | lo | hi]
// ---------------------------------------------------------------------------
__global__ __launch_bounds__(256) void prep_kernel(
    const float* __restrict__ enroll, const float* __restrict__ test)
{
    __shared__ float s[DD * (PB + 1)];
    __shared__ float scale[PB];

    int b = blockIdx.x;
    bool isA = (b < KT);
    int k = isA ? b : b - KT;
    const float* in = (isA ? enroll : test) + (size_t)k * DD * PB;

    for (int i = threadIdx.x; i < DD * PB; i += 256) {
        int d = i / PB, p = i - d * PB;
        s[d * (PB + 1) + p] = in[i];
    }
    __syncthreads();
    if (threadIdx.x < PB) {
        float ss = 0.f;
        #pragma unroll 8
        for (int d = 0; d < DD; d++) {
            float v = s[d * (PB + 1) + threadIdx.x];
            ss = fmaf(v, v, ss);
        }
        scale[threadIdx.x] = 1.0f / fmaxf(sqrtf(ss), 1e-12f);
    }
    __syncthreads();

    __half2* A2 = (__half2*)g_A;
    __half2* B2 = (__half2*)g_B;

    for (int i = threadIdx.x; i < PB * (DD / 2); i += 256) {
        int p = i >> 7;
        int d = (i & 127) * 2;
        float x0 = s[d * (PB + 1) + p] * scale[p];
        float x1 = s[(d + 1) * (PB + 1) + p] * scale[p];
        __half h0 = __float2half_rn(x0), h1 = __float2half_rn(x1);
        __half l0 = __float2half_rn(x0 - __half2float(h0));
        __half l1 = __float2half_rn(x1 - __half2float(h1));
        __half2 hp = __halves2half2(h0, h1);
        __half2 lp = __halves2half2(l0, l1);
        int row = k * PB + p;
        size_t base = (size_t)row * (KF / 2) + (d >> 1);
        if (isA) { A2[base] = hp; A2[base + 128] = hp; A2[base + 256] = lp; }
        else     { B2[base] = hp; B2[base + 128] = lp; B2[base + 256] = hp; }
    }
}

// ---------------------------------------------------------------------------
// Kernel 2: mma.sync GEMM (128x160 tile, K=768) + fused stage-1 epilogue.
// 8 warps = 2(M) x 4(N); warp tile 64x40 (one l-block per warp).
// ---------------------------------------------------------------------------
extern __shared__ __half smem_dyn[];

__device__ __forceinline__ void issue_loads(
    int tid, uint32_t aBase, uint32_t bBase,
    const char* gAp, const char* gBp, int c, int bf)
{
    #pragma unroll
    for (int it = 0; it < 4; it++) {          // A: 128 rows x 8 segs
        int idx = tid + it * 256;
        int row = idx >> 3, seg = idx & 7;
        uint32_t dst = aBase + bf * A_BUF_B + row * (ROWP * 2) + seg * 16;
        const char* src = gAp + (size_t)row * (KF * 2) + c * 128 + seg * 16;
        CP_ASYNC16(dst, src);
    }
    #pragma unroll
    for (int it = 0; it < 5; it++) {          // B: 160 rows x 8 segs
        int idx = tid + it * 256;
        int row = idx >> 3, seg = idx & 7;
        uint32_t dst = bBase + bf * B_BUF_B + row * (ROWP * 2) + seg * 16;
        const char* src = gBp + (size_t)row * (KF * 2) + c * 128 + seg * 16;
        CP_ASYNC16(dst, src);
    }
    CP_COMMIT();
}

__global__ __launch_bounds__(256) void gemm_kernel(
    const float* __restrict__ fc1w, const float* __restrict__ fc1b,
    const float* __restrict__ fc2w)
{
    const int tid = threadIdx.x;
    const int lane = tid & 31;
    const int wid = tid >> 5;
    const int warpM = wid >> 2;     // 0..1
    const int warpN = wid & 3;      // 0..3
    const int mt = blockIdx.x;
    const int nt = blockIdx.y;

    __half* sA = smem_dyn;
    __half* sB = smem_dyn + 2 * TM * ROWP;
    const uint32_t aBase = smem_u32(sA);
    const uint32_t bBase = smem_u32(sB);

    const char* gAp = (const char*)g_A + (size_t)mt * TM * KF * 2;
    const char* gBp = (const char*)g_B + (size_t)nt * TN * KF * 2;

    float acc[4][5][4];
    #pragma unroll
    for (int i = 0; i < 4; i++)
        #pragma unroll
        for (int j = 0; j < 5; j++)
            #pragma unroll
            for (int e = 0; e < 4; e++) acc[i][j][e] = 0.f;

    // ldmatrix per-lane byte offsets (within a buffer)
    const int arow = lane & 15;
    const int acol = (lane & 16) ? 8 : 0;
    uint32_t aOff[4];
    #pragma unroll
    for (int mf = 0; mf < 4; mf++)
        aOff[mf] = ((warpM * 64 + mf * 16 + arow) * ROWP + acol) * 2;

    const int bkc = (lane & 8) ? 8 : 0;
    uint32_t bOff4[2];
    #pragma unroll
    for (int g = 0; g < 2; g++) {
        int n = warpN * 40 + g * 16 + (lane & 7) + ((lane & 16) ? 8 : 0);
        bOff4[g] = (n * ROWP + bkc) * 2;
    }
    uint32_t bOff2 = ((warpN * 40 + 32 + (lane & 7)) * ROWP + bkc) * 2;

    issue_loads(tid, aBase, bBase, gAp, gBp, 0, 0);

    for (int c = 0; c < NCH; c++) {
        const int bf = c & 1;
        if (c + 1 < NCH) {
            issue_loads(tid, aBase, bBase, gAp, gBp, c + 1, bf ^ 1);
            CP_WAIT1();
        } else {
            CP_WAIT0();
        }
        __syncthreads();

        const uint32_t aB = aBase + bf * A_BUF_B;
        const uint32_t bB = bBase + bf * B_BUF_B;
        #pragma unroll
        for (int ks = 0; ks < 4; ks++) {
            const uint32_t kadd = ks * 32;   // 16 halves
            uint32_t af[4][4];
            #pragma unroll
            for (int mf = 0; mf < 4; mf++)
                LDSM4(af[mf][0], af[mf][1], af[mf][2], af[mf][3],
                      aB + aOff[mf] + kadd);
            uint32_t bw[5][2];
            LDSM4(bw[0][0], bw[0][1], bw[1][0], bw[1][1], bB + bOff4[0] + kadd);
            LDSM4(bw[2][0], bw[2][1], bw[3][0], bw[3][1], bB + bOff4[1] + kadd);
            LDSM2(bw[4][0], bw[4][1], bB + bOff2 + kadd);

            #pragma unroll
            for (int mf = 0; mf < 4; mf++)
                #pragma unroll
                for (int nf = 0; nf < 5; nf++)
                    MMA16816(acc[mf][nf], af[mf][0], af[mf][1], af[mf][2],
                             af[mf][3], bw[nf][0], bw[nf][1]);
        }
        __syncthreads();
    }

    // ---- fused stage-1 epilogue: gate, masked mean over the 40-wide l-block
    float w1[CG], b1[CG], w2[CG];
    #pragma unroll
    for (int q = 0; q < CG; q++) { w1[q] = fc1w[q]; b1[q] = fc1b[q]; w2[q] = fc2w[q]; }

    const int g = lane >> 2;     // row within 8
    const int tig = lane & 3;    // col quad
    const int lcol = nt * 4 + warpN;

    #pragma unroll
    for (int mf = 0; mf < 4; mf++) {
        float s0 = 0.f, c0 = 0.f, s1 = 0.f, c1 = 0.f;
        #pragma unroll
        for (int nf = 0; nf < 5; nf++) {
            float x0 = acc[mf][nf][0], x1 = acc[mf][nf][1];
            float x2 = acc[mf][nf][2], x3 = acc[mf][nf][3];
            c0 += ((x0 != 0.f) ? 1.f : 0.f) + ((x1 != 0.f) ? 1.f : 0.f);
            c1 += ((x2 != 0.f) ? 1.f : 0.f) + ((x3 != 0.f) ? 1.f : 0.f);
            s0 = fmaf(gate_fn(x0, w1, b1, w2), x0, s0);
            s0 = fmaf(gate_fn(x1, w1, b1, w2), x1, s0);
            s1 = fmaf(gate_fn(x2, w1, b1, w2), x2, s1);
            s1 = fmaf(gate_fn(x3, w1, b1, w2), x3, s1);
        }
        // reduce over the 4 col-quads (tig)
        #pragma unroll
        for (int o = 1; o <= 2; o <<= 1) {
            s0 += __shfl_xor_sync(0xffffffffu, s0, o);
            c0 += __shfl_xor_sync(0xffffffffu, c0, o);
            s1 += __shfl_xor_sync(0xffffffffu, s1, o);
            c1 += __shfl_xor_sync(0xffffffffu, c1, o);
        }
        if (tig == 0) {
            int m0 = mt * TM + warpM * 64 + mf * 16 + g;
            g_pho1[(size_t)m0 * KT + lcol] = s0 / (c0 + 1e-6f);
            g_pho1[(size_t)(m0 + 8) * KT + lcol] = s1 / (c1 + 1e-6f);
        }
    }
}

// ---------------------------------------------------------------------------
// Kernel 3: stage-2 gate + masked mean over i (40). One warp per (k,l).
// ---------------------------------------------------------------------------
__global__ __launch_bounds__(256) void stage2_kernel(
    const float* __restrict__ fc1w, const float* __restrict__ fc1b,
    const float* __restrict__ fc2w, float* __restrict__ out)
{
    int pair = blockIdx.x * 8 + (threadIdx.x >> 5);
    int lid = threadIdx.x & 31;
    int k = pair / KT, l = pair % KT;

    float w1[CG], b1[CG], w2[CG];
    #pragma unroll
    for (int q = 0; q < CG; q++) { w1[q] = fc1w[q]; b1[q] = fc1b[q]; w2[q] = fc2w[q]; }

    float s = 0.f, cnt = 0.f;
    {
        float v = g_pho1[(size_t)(k * PB + lid) * KT + l];
        cnt += (v != 0.0f) ? 1.0f : 0.0f;
        s = fmaf(gate_fn(v, w1, b1, w2), v, s);
    }
    if (lid < PB - 32) {
        float v = g_pho1[(size_t)(k * PB + 32 + lid) * KT + l];
        cnt += (v != 0.0f) ? 1.0f : 0.0f;
        s = fmaf(gate_fn(v, w1, b1, w2), v, s);
    }
    #pragma unroll
    for (int o = 16; o; o >>= 1) {
        s   += __shfl_down_sync(0xffffffffu, s, o);
        cnt += __shfl_down_sync(0xffffffffu, cnt, o);
    }
    if (lid == 0) out[k * KT + l] = s / (cnt + 1e-6f);
}

// ---------------------------------------------------------------------------
extern "C" void kernel_launch(void* const* d_in, const int* in_sizes, int n_in,
                              void* d_out, int out_size)
{
    const float* enroll = (const float*)d_in[0];
    const float* test   = (const float*)d_in[1];
    const float* fc1w   = (const float*)d_in[2];
    const float* fc1b   = (const float*)d_in[3];
    const float* fc2w   = (const float*)d_in[4];
    float* out = (float*)d_out;

    cudaFuncSetAttribute(gemm_kernel,
                         cudaFuncAttributeMaxDynamicSharedMemorySize, SMEM_BYTES);

    prep_kernel<<<2 * KT, 256>>>(enroll, test);
    dim3 grid(NMT, NNT);
    gemm_kernel<<<grid, 256, SMEM_BYTES>>>(fc1w, fc1b, fc2w);
    stage2_kernel<<<(KT * KT) / 8, 256>>>(fc1w, fc1b, fc2w, out);
}

// round 6
// speedup vs baseline: 3.5491x; 1.1195x over previous
#include <cuda_runtime.h>
#include <cuda_fp16.h>
#include <cstdint>

#define KT 96
#define DD 256
#define PB 40
#define CG 8

#define MTOT 3840          // KT*PB
#define KA   512           // A split K: [Ah | Al]
#define KB   256           // B stored once (Bh); chunks reused
#define TM   128
#define TN   160
#define NCH  8             // K chunks of 64 halves
#define ROWP 72            // padded smem row stride (halves) = 144B
#define NMT  (MTOT / TM)   // 30
#define NNT  (MTOT / TN)   // 24

#define A_BUF_B (TM * ROWP * 2)   // 18432
#define B_BUF_B (TN * ROWP * 2)   // 23040
#define LUT_N   1024
#define LUT_B   (LUT_N * 8)       // float2 table, 8KB
#define SMEM_BYTES (LUT_B + 2 * (A_BUF_B + B_BUF_B))  // 91136

__device__ __align__(16) __half g_A[MTOT * KA];
__device__ __align__(16) __half g_B[MTOT * KB];
__device__ float g_pho1[MTOT * KT];
__device__ float g_scale[192 * PB];
__device__ float g_lutV[LUT_N + 1];

// ---------------------------------------------------------------------------
__device__ __forceinline__ uint32_t smem_u32(const void* p) {
    uint32_t a;
    asm("{ .reg .u64 t; cvta.to.shared.u64 t, %1; cvt.u32.u64 %0, t; }"
        : "=r"(a) : "l"(p));
    return a;
}
#define CP_ASYNC16(dst, src) \
    asm volatile("cp.async.cg.shared.global [%0], [%1], 16;" \
                 :: "r"(dst), "l"(src) : "memory")
#define CP_COMMIT() asm volatile("cp.async.commit_group;" ::: "memory")
#define CP_WAIT1()  asm volatile("cp.async.wait_group 1;" ::: "memory")
#define CP_WAIT0()  asm volatile("cp.async.wait_group 0;" ::: "memory")

#define LDSM4(r0, r1, r2, r3, a) \
    asm volatile("ldmatrix.sync.aligned.m8n8.x4.shared.b16 {%0,%1,%2,%3}, [%4];" \
                 : "=r"(r0), "=r"(r1), "=r"(r2), "=r"(r3) : "r"(a))
#define LDSM2(r0, r1, a) \
    asm volatile("ldmatrix.sync.aligned.m8n8.x2.shared.b16 {%0,%1}, [%2];" \
                 : "=r"(r0), "=r"(r1) : "r"(a))
#define MMA16816(c, a0, a1, a2, a3, b0, b1) \
    asm volatile("mma.sync.aligned.m16n8k16.row.col.f32.f16.f16.f32 " \
                 "{%0,%1,%2,%3},{%4,%5,%6,%7},{%8,%9},{%0,%1,%2,%3};" \
                 : "+f"((c)[0]), "+f"((c)[1]), "+f"((c)[2]), "+f"((c)[3]) \
                 : "r"(a0), "r"(a1), "r"(a2), "r"(a3), "r"(b0), "r"(b1))

__device__ __forceinline__ float tanh_fast(float x) {
    float y;
    asm("tanh.approx.f32 %0, %1;" : "=f"(y) : "f"(x));
    return y;
}
// exact-form gate (used for LUT build and tiny stage-2)
__device__ __forceinline__ float gate_fn(float x, const float w1[CG],
                                         const float b1[CG], const float w2[CG]) {
    float g = 0.f;
    #pragma unroll
    for (int c = 0; c < CG; c++)
        g = fmaf(w2[c], tanh_fast(fmaf(x, w1[c], b1[c])), g);
    return g;
}

// ---------------------------------------------------------------------------
// Kernel 0: build gate LUT over [-4, 4], 1024 intervals (1025 knots).
// ---------------------------------------------------------------------------
__global__ void lut_kernel(const float* __restrict__ fc1w,
                           const float* __restrict__ fc1b,
                           const float* __restrict__ fc2w)
{
    float w1[CG], b1[CG], w2[CG];
    #pragma unroll
    for (int q = 0; q < CG; q++) { w1[q] = fc1w[q]; b1[q] = fc1b[q]; w2[q] = fc2w[q]; }
    for (int i = threadIdx.x; i <= LUT_N; i += blockDim.x) {
        float x = -4.0f + (float)i * (8.0f / LUT_N);
        float g = 0.f;
        #pragma unroll
        for (int c = 0; c < CG; c++)
            g = fmaf(w2[c], tanhf(fmaf(x, w1[c], b1[c])), g);
        g_lutV[i] = g;
    }
}

// ---------------------------------------------------------------------------
// Kernel 1a: column norms -> g_scale[b][p]. One block per (b), 320 threads.
// ---------------------------------------------------------------------------
__global__ __launch_bounds__(320) void scale_kernel(
    const float* __restrict__ enroll, const float* __restrict__ test)
{
    __shared__ float sred[320];
    int b = blockIdx.x;
    const float* in = ((b < KT) ? enroll : test)
                    + (size_t)((b < KT) ? b : b - KT) * DD * PB;
    int t = threadIdx.x;
    int p = t % PB, j = t / PB;           // j in [0,8)
    float ss = 0.f;
    #pragma unroll 8
    for (int i = 0; i < 32; i++) {
        float v = in[(j * 32 + i) * PB + p];
        ss = fmaf(v, v, ss);
    }
    sred[t] = ss;
    __syncthreads();
    if (t < PB) {
        float s = 0.f;
        #pragma unroll
        for (int q = 0; q < 8; q++) s += sred[t + q * PB];
        g_scale[b * PB + t] = 1.0f / fmaxf(sqrtf(s), 1e-12f);
    }
}

// ---------------------------------------------------------------------------
// Kernel 1b: scatter normalized fp16 splits. grid (192, 4), 320 threads.
// Block (b, seg) handles d in [seg*64, seg*64+64).
// A row: [Ah(256) | Al(256)] ; B row: [Bh(256)]
// ---------------------------------------------------------------------------
__global__ __launch_bounds__(320) void scatter_kernel(
    const float* __restrict__ enroll, const float* __restrict__ test)
{
    __shared__ float s[64][PB + 1];
    int b = blockIdx.x, seg = blockIdx.y;
    bool isA = (b < KT);
    int k = isA ? b : b - KT;
    const float* in = (isA ? enroll : test)
                    + (size_t)k * DD * PB + (size_t)seg * 64 * PB;
    int t = threadIdx.x;

    #pragma unroll
    for (int i = 0; i < 8; i++) {
        int idx = t + i * 320;
        s[idx / PB][idx % PB] = in[idx];
    }
    __syncthreads();

    int p = t >> 3;           // 0..39
    int q = t & 7;            // 0..7
    float sc = g_scale[b * PB + p];
    int row = k * PB + p;
    __half2* A2 = (__half2*)g_A + (size_t)row * (KA / 2);
    __half2* B2 = (__half2*)g_B + (size_t)row * (KB / 2);

    #pragma unroll
    for (int w = 0; w < 4; w++) {
        int u = q + w * 8;                 // half2 unit within the 64-d segment
        float x0 = s[u * 2][p] * sc;
        float x1 = s[u * 2 + 1][p] * sc;
        __half h0 = __float2half_rn(x0), h1 = __float2half_rn(x1);
        __half2 hp = __halves2half2(h0, h1);
        int gu = seg * 32 + u;             // global half2 index (of 128)
        if (isA) {
            __half l0 = __float2half_rn(x0 - __half2float(h0));
            __half l1 = __float2half_rn(x1 - __half2float(h1));
            A2[gu] = hp;
            A2[gu + 128] = __halves2half2(l0, l1);
        } else {
            B2[gu] = hp;
        }
    }
}

// ---------------------------------------------------------------------------
// Kernel 2: mma.sync GEMM (128x160, K=512; B chunks reused) + LUT epilogue.
// ---------------------------------------------------------------------------
extern __shared__ char smem_dyn[];

__device__ __forceinline__ void issue_loads(
    int tid, uint32_t aBase, uint32_t bBase,
    const char* gAp, const char* gBp, int c, int bf)
{
    #pragma unroll
    for (int it = 0; it < 4; it++) {
        int idx = tid + it * 256;
        int row = idx >> 3, seg = idx & 7;
        uint32_t dst = aBase + bf * A_BUF_B + row * (ROWP * 2) + seg * 16;
        const char* src = gAp + (size_t)row * (KA * 2) + c * 128 + seg * 16;
        CP_ASYNC16(dst, src);
    }
    const int cb = c & 3;
    #pragma unroll
    for (int it = 0; it < 5; it++) {
        int idx = tid + it * 256;
        int row = idx >> 3, seg = idx & 7;
        uint32_t dst = bBase + bf * B_BUF_B + row * (ROWP * 2) + seg * 16;
        const char* src = gBp + (size_t)row * (KB * 2) + cb * 128 + seg * 16;
        CP_ASYNC16(dst, src);
    }
    CP_COMMIT();
}

__global__ __launch_bounds__(256) void gemm_kernel()
{
    const int tid = threadIdx.x;
    const int lane = tid & 31;
    const int wid = tid >> 5;
    const int warpM = wid >> 2;
    const int warpN = wid & 3;
    const int mt = blockIdx.x;
    const int nt = blockIdx.y;

    float2* lut = (float2*)smem_dyn;
    __half* sA = (__half*)(smem_dyn + LUT_B);
    __half* sB = (__half*)(smem_dyn + LUT_B + 2 * A_BUF_B);
    const uint32_t aBase = smem_u32(sA);
    const uint32_t bBase = smem_u32(sB);

    const char* gAp = (const char*)g_A + (size_t)mt * TM * KA * 2;
    const char* gBp = (const char*)g_B + (size_t)nt * TN * KB * 2;

    issue_loads(tid, aBase, bBase, gAp, gBp, 0, 0);

    // build smem LUT (overlaps with first cp.async group)
    for (int i = tid; i < LUT_N; i += 256)
        lut[i] = make_float2(g_lutV[i], g_lutV[i + 1]);

    float acc[4][5][4];
    #pragma unroll
    for (int i = 0; i < 4; i++)
        #pragma unroll
        for (int j = 0; j < 5; j++)
            #pragma unroll
            for (int e = 0; e < 4; e++) acc[i][j][e] = 0.f;

    const int arow = lane & 15;
    const int acol = (lane & 16) ? 8 : 0;
    uint32_t aOff[4];
    #pragma unroll
    for (int mf = 0; mf < 4; mf++)
        aOff[mf] = ((warpM * 64 + mf * 16 + arow) * ROWP + acol) * 2;

    const int bkc = (lane & 8) ? 8 : 0;
    uint32_t bOff4[2];
    #pragma unroll
    for (int g = 0; g < 2; g++) {
        int n = warpN * 40 + g * 16 + (lane & 7) + ((lane & 16) ? 8 : 0);
        bOff4[g] = (n * ROWP + bkc) * 2;
    }
    uint32_t bOff2 = ((warpN * 40 + 32 + (lane & 7)) * ROWP + bkc) * 2;

    for (int c = 0; c < NCH; c++) {
        const int bf = c & 1;
        if (c + 1 < NCH) {
            issue_loads(tid, aBase, bBase, gAp, gBp, c + 1, bf ^ 1);
            CP_WAIT1();
        } else {
            CP_WAIT0();
        }
        __syncthreads();

        const uint32_t aB = aBase + bf * A_BUF_B;
        const uint32_t bB = bBase + bf * B_BUF_B;
        #pragma unroll
        for (int ks = 0; ks < 4; ks++) {
            const uint32_t kadd = ks * 32;
            uint32_t af[4][4];
            #pragma unroll
            for (int mf = 0; mf < 4; mf++)
                LDSM4(af[mf][0], af[mf][1], af[mf][2], af[mf][3],
                      aB + aOff[mf] + kadd);
            uint32_t bw[5][2];
            LDSM4(bw[0][0], bw[0][1], bw[1][0], bw[1][1], bB + bOff4[0] + kadd);
            LDSM4(bw[2][0], bw[2][1], bw[3][0], bw[3][1], bB + bOff4[1] + kadd);
            LDSM2(bw[4][0], bw[4][1], bB + bOff2 + kadd);
            #pragma unroll
            for (int mf = 0; mf < 4; mf++)
                #pragma unroll
                for (int nf = 0; nf < 5; nf++)
                    MMA16816(acc[mf][nf], af[mf][0], af[mf][1], af[mf][2],
                             af[mf][3], bw[nf][0], bw[nf][1]);
        }
        __syncthreads();
    }

    // ---- epilogue: LUT gate, masked mean over the 40-wide l-block
    const int g = lane >> 2;
    const int tig = lane & 3;
    const int lcol = nt * 4 + warpN;

    #pragma unroll
    for (int mf = 0; mf < 4; mf++) {
        float s0 = 0.f, c0 = 0.f, s1 = 0.f, c1 = 0.f;
        #pragma unroll
        for (int nf = 0; nf < 5; nf++) {
            #pragma unroll
            for (int e = 0; e < 4; e++) {
                float x = acc[mf][nf][e];
                float t = fmaf(x, 128.f, 512.f);
                t = fminf(fmaxf(t, 0.f), 1023.999f);
                int i = (int)t;
                float f = t - (float)i;
                float2 pr = lut[i];
                float gx = fmaf(f, pr.y - pr.x, pr.x);
                float nz = (x != 0.f) ? 1.f : 0.f;
                if (e < 2) { c0 += nz; s0 = fmaf(gx, x, s0); }
                else       { c1 += nz; s1 = fmaf(gx, x, s1); }
            }
        }
        #pragma unroll
        for (int o = 1; o <= 2; o <<= 1) {
            s0 += __shfl_xor_sync(0xffffffffu, s0, o);
            c0 += __shfl_xor_sync(0xffffffffu, c0, o);
            s1 += __shfl_xor_sync(0xffffffffu, s1, o);
            c1 += __shfl_xor_sync(0xffffffffu, c1, o);
        }
        if (tig == 0) {
            int m0 = mt * TM + warpM * 64 + mf * 16 + g;
            g_pho1[(size_t)m0 * KT + lcol] = s0 / (c0 + 1e-6f);
            g_pho1[(size_t)(m0 + 8) * KT + lcol] = s1 / (c1 + 1e-6f);
        }
    }
}

// ---------------------------------------------------------------------------
// Kernel 3: stage-2 gate + masked mean. One warp per (k,l).
// ---------------------------------------------------------------------------
__global__ __launch_bounds__(256) void stage2_kernel(
    const float* __restrict__ fc1w, const float* __restrict__ fc1b,
    const float* __restrict__ fc2w, float* __restrict__ out)
{
    int pair = blockIdx.x * 8 + (threadIdx.x >> 5);
    int lid = threadIdx.x & 31;
    int k = pair / KT, l = pair % KT;

    float w1[CG], b1[CG], w2[CG];
    #pragma unroll
    for (int q = 0; q < CG; q++) { w1[q] = fc1w[q]; b1[q] = fc1b[q]; w2[q] = fc2w[q]; }

    float s = 0.f, cnt = 0.f;
    {
        float v = g_pho1[(size_t)(k * PB + lid) * KT + l];
        cnt += (v != 0.0f) ? 1.0f : 0.0f;
        s = fmaf(gate_fn(v, w1, b1, w2), v, s);
    }
    if (lid < PB - 32) {
        float v = g_pho1[(size_t)(k * PB + 32 + lid) * KT + l];
        cnt += (v != 0.0f) ? 1.0f : 0.0f;
        s = fmaf(gate_fn(v, w1, b1, w2), v, s);
    }
    #pragma unroll
    for (int o = 16; o; o >>= 1) {
        s   += __shfl_down_sync(0xffffffffu, s, o);
        cnt += __shfl_down_sync(0xffffffffu, cnt, o);
    }
    if (lid == 0) out[k * KT + l] = s / (cnt + 1e-6f);
}

// ---------------------------------------------------------------------------
extern "C" void kernel_launch(void* const* d_in, const int* in_sizes, int n_in,
                              void* d_out, int out_size)
{
    const float* enroll = (const float*)d_in[0];
    const float* test   = (const float*)d_in[1];
    const float* fc1w   = (const float*)d_in[2];
    const float* fc1b   = (const float*)d_in[3];
    const float* fc2w   = (const float*)d_in[4];
    float* out = (float*)d_out;

    cudaFuncSetAttribute(gemm_kernel,
                         cudaFuncAttributeMaxDynamicSharedMemorySize, SMEM_BYTES);

    lut_kernel<<<1, 1024>>>(fc1w, fc1b, fc2w);
    scale_kernel<<<2 * KT, 320>>>(enroll, test);
    scatter_kernel<<<dim3(2 * KT, 4), 320>>>(enroll, test);
    dim3 grid(NMT, NNT);
    gemm_kernel<<<grid, 256, SMEM_BYTES>>>();
    stage2_kernel<<<(KT * KT) / 8, 256>>>(fc1w, fc1b, fc2w, out);
}

// round 7
// speedup vs baseline: 4.0800x; 1.1496x over previous
#include <cuda_runtime.h>
#include <cuda_fp16.h>
#include <cstdint>

#define KT 96
#define DD 256
#define PB 40
#define CG 8

#define MTOT 3840          // KT*PB
#define KA   512           // A split K: [Ah | Al]
#define KB   256           // B stored once (Bh); chunks reused
#define TM   128
#define TN   160
#define NCH  8             // K chunks of 64 halves
#define ROWP 72            // padded smem row stride (halves) = 144B
#define NMT  (MTOT / TM)   // 30
#define NNT  (MTOT / TN)   // 24

#define A_BUF_B (TM * ROWP * 2)   // 18432
#define B_BUF_B (TN * ROWP * 2)   // 23040
#define LUT_N   1024
#define LUT_B   (LUT_N * 8)       // float2 table, 8KB
#define SMEM_BYTES (LUT_B + 2 * (A_BUF_B + B_BUF_B))  // 91136

__device__ __align__(16) __half g_A[MTOT * KA];
__device__ __align__(16) __half g_B[MTOT * KB];
__device__ float g_pho1[MTOT * KT];
__device__ float g_scale[192 * PB];
__device__ float g_lutV[LUT_N + 1];

// ---------------------------------------------------------------------------
__device__ __forceinline__ uint32_t smem_u32(const void* p) {
    uint32_t a;
    asm("{ .reg .u64 t; cvta.to.shared.u64 t, %1; cvt.u32.u64 %0, t; }"
        : "=r"(a) : "l"(p));
    return a;
}
#define CP_ASYNC16(dst, src) \
    asm volatile("cp.async.cg.shared.global [%0], [%1], 16;" \
                 :: "r"(dst), "l"(src) : "memory")
#define CP_COMMIT() asm volatile("cp.async.commit_group;" ::: "memory")
#define CP_WAIT1()  asm volatile("cp.async.wait_group 1;" ::: "memory")
#define CP_WAIT0()  asm volatile("cp.async.wait_group 0;" ::: "memory")

#define LDSM4(r0, r1, r2, r3, a) \
    asm volatile("ldmatrix.sync.aligned.m8n8.x4.shared.b16 {%0,%1,%2,%3}, [%4];" \
                 : "=r"(r0), "=r"(r1), "=r"(r2), "=r"(r3) : "r"(a))
#define LDSM2(r0, r1, a) \
    asm volatile("ldmatrix.sync.aligned.m8n8.x2.shared.b16 {%0,%1}, [%2];" \
                 : "=r"(r0), "=r"(r1) : "r"(a))
#define MMA16816(c, a0, a1, a2, a3, b0, b1) \
    asm volatile("mma.sync.aligned.m16n8k16.row.col.f32.f16.f16.f32 " \
                 "{%0,%1,%2,%3},{%4,%5,%6,%7},{%8,%9},{%0,%1,%2,%3};" \
                 : "+f"((c)[0]), "+f"((c)[1]), "+f"((c)[2]), "+f"((c)[3]) \
                 : "r"(a0), "r"(a1), "r"(a2), "r"(a3), "r"(b0), "r"(b1))

__device__ __forceinline__ float tanh_fast(float x) {
    float y;
    asm("tanh.approx.f32 %0, %1;" : "=f"(y) : "f"(x));
    return y;
}
__device__ __forceinline__ float gate_fn(float x, const float w1[CG],
                                         const float b1[CG], const float w2[CG]) {
    float g = 0.f;
    #pragma unroll
    for (int c = 0; c < CG; c++)
        g = fmaf(w2[c], tanh_fast(fmaf(x, w1[c], b1[c])), g);
    return g;
}

// ---------------------------------------------------------------------------
// Kernel 0: build gate LUT over [-4, 4], 1024 intervals (1025 knots).
// ---------------------------------------------------------------------------
__global__ void lut_kernel(const float* __restrict__ fc1w,
                           const float* __restrict__ fc1b,
                           const float* __restrict__ fc2w)
{
    float w1[CG], b1[CG], w2[CG];
    #pragma unroll
    for (int q = 0; q < CG; q++) { w1[q] = fc1w[q]; b1[q] = fc1b[q]; w2[q] = fc2w[q]; }
    for (int i = threadIdx.x; i <= LUT_N; i += blockDim.x) {
        float x = -4.0f + (float)i * (8.0f / LUT_N);
        float g = 0.f;
        #pragma unroll
        for (int c = 0; c < CG; c++)
            g = fmaf(w2[c], tanhf(fmaf(x, w1[c], b1[c])), g);
        g_lutV[i] = g;
    }
}

// ---------------------------------------------------------------------------
// Kernel 1a: column norms -> g_scale[b][p].
// ---------------------------------------------------------------------------
__global__ __launch_bounds__(320) void scale_kernel(
    const float* __restrict__ enroll, const float* __restrict__ test)
{
    __shared__ float sred[320];
    int b = blockIdx.x;
    const float* in = ((b < KT) ? enroll : test)
                    + (size_t)((b < KT) ? b : b - KT) * DD * PB;
    int t = threadIdx.x;
    int p = t % PB, j = t / PB;
    float ss = 0.f;
    #pragma unroll 8
    for (int i = 0; i < 32; i++) {
        float v = in[(j * 32 + i) * PB + p];
        ss = fmaf(v, v, ss);
    }
    sred[t] = ss;
    __syncthreads();
    if (t < PB) {
        float s = 0.f;
        #pragma unroll
        for (int q = 0; q < 8; q++) s += sred[t + q * PB];
        g_scale[b * PB + t] = 1.0f / fmaxf(sqrtf(s), 1e-12f);
    }
}

// ---------------------------------------------------------------------------
// Kernel 1b: scatter normalized fp16 splits. grid (192, 4), 320 threads.
// ---------------------------------------------------------------------------
__global__ __launch_bounds__(320) void scatter_kernel(
    const float* __restrict__ enroll, const float* __restrict__ test)
{
    __shared__ float s[64][PB + 1];
    int b = blockIdx.x, seg = blockIdx.y;
    bool isA = (b < KT);
    int k = isA ? b : b - KT;
    const float* in = (isA ? enroll : test)
                    + (size_t)k * DD * PB + (size_t)seg * 64 * PB;
    int t = threadIdx.x;

    #pragma unroll
    for (int i = 0; i < 8; i++) {
        int idx = t + i * 320;
        s[idx / PB][idx % PB] = in[idx];
    }
    __syncthreads();

    int p = t >> 3;
    int q = t & 7;
    float sc = g_scale[b * PB + p];
    int row = k * PB + p;
    __half2* A2 = (__half2*)g_A + (size_t)row * (KA / 2);
    __half2* B2 = (__half2*)g_B + (size_t)row * (KB / 2);

    #pragma unroll
    for (int w = 0; w < 4; w++) {
        int u = q + w * 8;
        float x0 = s[u * 2][p] * sc;
        float x1 = s[u * 2 + 1][p] * sc;
        __half h0 = __float2half_rn(x0), h1 = __float2half_rn(x1);
        __half2 hp = __halves2half2(h0, h1);
        int gu = seg * 32 + u;
        if (isA) {
            __half l0 = __float2half_rn(x0 - __half2float(h0));
            __half l1 = __float2half_rn(x1 - __half2float(h1));
            A2[gu] = hp;
            A2[gu + 128] = __halves2half2(l0, l1);
        } else {
            B2[gu] = hp;
        }
    }
}

// ---------------------------------------------------------------------------
// Kernel 2: mma.sync GEMM (128x160, K=512; B chunks reused) + LUT epilogue.
// __launch_bounds__(256, 2): cap regs at 128 -> 2 CTAs/SM (register file).
// ---------------------------------------------------------------------------
extern __shared__ char smem_dyn[];

__device__ __forceinline__ void issue_loads(
    int tid, uint32_t aBase, uint32_t bBase,
    const char* gAp, const char* gBp, int c, int bf)
{
    #pragma unroll
    for (int it = 0; it < 4; it++) {
        int idx = tid + it * 256;
        int row = idx >> 3, seg = idx & 7;
        uint32_t dst = aBase + bf * A_BUF_B + row * (ROWP * 2) + seg * 16;
        const char* src = gAp + (size_t)row * (KA * 2) + c * 128 + seg * 16;
        CP_ASYNC16(dst, src);
    }
    const int cb = c & 3;
    #pragma unroll
    for (int it = 0; it < 5; it++) {
        int idx = tid + it * 256;
        int row = idx >> 3, seg = idx & 7;
        uint32_t dst = bBase + bf * B_BUF_B + row * (ROWP * 2) + seg * 16;
        const char* src = gBp + (size_t)row * (KB * 2) + cb * 128 + seg * 16;
        CP_ASYNC16(dst, src);
    }
    CP_COMMIT();
}

__global__ __launch_bounds__(256, 2) void gemm_kernel()
{
    const int tid = threadIdx.x;
    const int lane = tid & 31;
    const int wid = tid >> 5;
    const int warpM = wid >> 2;
    const int warpN = wid & 3;
    const int mt = blockIdx.x;
    const int nt = blockIdx.y;

    float2* lut = (float2*)smem_dyn;
    __half* sA = (__half*)(smem_dyn + LUT_B);
    __half* sB = (__half*)(smem_dyn + LUT_B + 2 * A_BUF_B);
    const uint32_t aBase = smem_u32(sA);
    const uint32_t bBase = smem_u32(sB);

    const char* gAp = (const char*)g_A + (size_t)mt * TM * KA * 2;
    const char* gBp = (const char*)g_B + (size_t)nt * TN * KB * 2;

    issue_loads(tid, aBase, bBase, gAp, gBp, 0, 0);

    for (int i = tid; i < LUT_N; i += 256)
        lut[i] = make_float2(g_lutV[i], g_lutV[i + 1]);

    float acc[4][5][4];
    #pragma unroll
    for (int i = 0; i < 4; i++)
        #pragma unroll
        for (int j = 0; j < 5; j++)
            #pragma unroll
            for (int e = 0; e < 4; e++) acc[i][j][e] = 0.f;

    const int arow = lane & 15;
    const int acol = (lane & 16) ? 8 : 0;
    const uint32_t aOff0 = ((warpM * 64 + arow) * ROWP + acol) * 2;

    const int bkc = (lane & 8) ? 8 : 0;
    const int bsel = (lane & 16) ? 8 : 0;
    const uint32_t bOff0 = ((warpN * 40 + (lane & 7) + bsel) * ROWP + bkc) * 2;
    const uint32_t bOff2 = ((warpN * 40 + 32 + (lane & 7)) * ROWP + bkc) * 2;

    for (int c = 0; c < NCH; c++) {
        const int bf = c & 1;
        if (c + 1 < NCH) {
            issue_loads(tid, aBase, bBase, gAp, gBp, c + 1, bf ^ 1);
            CP_WAIT1();
        } else {
            CP_WAIT0();
        }
        __syncthreads();

        const uint32_t aB = aBase + bf * A_BUF_B;
        const uint32_t bB = bBase + bf * B_BUF_B;
        #pragma unroll
        for (int ks = 0; ks < 4; ks++) {
            const uint32_t kadd = ks * 32;
            uint32_t af[4][4];
            #pragma unroll
            for (int mf = 0; mf < 4; mf++)
                LDSM4(af[mf][0], af[mf][1], af[mf][2], af[mf][3],
                      aB + aOff0 + mf * (16 * ROWP * 2) + kadd);
            uint32_t bw[5][2];
            LDSM4(bw[0][0], bw[0][1], bw[1][0], bw[1][1], bB + bOff0 + kadd);
            LDSM4(bw[2][0], bw[2][1], bw[3][0], bw[3][1],
                  bB + bOff0 + 16 * ROWP * 2 + kadd);
            LDSM2(bw[4][0], bw[4][1], bB + bOff2 + kadd);
            #pragma unroll
            for (int mf = 0; mf < 4; mf++)
                #pragma unroll
                for (int nf = 0; nf < 5; nf++)
                    MMA16816(acc[mf][nf], af[mf][0], af[mf][1], af[mf][2],
                             af[mf][3], bw[nf][0], bw[nf][1]);
        }
        __syncthreads();
    }

    // ---- epilogue: LUT gate, masked mean over the 40-wide l-block
    const int g = lane >> 2;
    const int tig = lane & 3;
    const int lcol = nt * 4 + warpN;

    #pragma unroll
    for (int mf = 0; mf < 4; mf++) {
        float s0 = 0.f, c0 = 0.f, s1 = 0.f, c1 = 0.f;
        #pragma unroll
        for (int nf = 0; nf < 5; nf++) {
            #pragma unroll
            for (int e = 0; e < 4; e++) {
                float x = acc[mf][nf][e];
                float t = fmaf(x, 128.f, 512.f);
                t = fminf(fmaxf(t, 0.f), 1023.999f);
                int i = (int)t;
                float f = t - (float)i;
                float2 pr = lut[i];
                float gx = fmaf(f, pr.y - pr.x, pr.x);
                float nz = (x != 0.f) ? 1.f : 0.f;
                if (e < 2) { c0 += nz; s0 = fmaf(gx, x, s0); }
                else       { c1 += nz; s1 = fmaf(gx, x, s1); }
            }
        }
        #pragma unroll
        for (int o = 1; o <= 2; o <<= 1) {
            s0 += __shfl_xor_sync(0xffffffffu, s0, o);
            c0 += __shfl_xor_sync(0xffffffffu, c0, o);
            s1 += __shfl_xor_sync(0xffffffffu, s1, o);
            c1 += __shfl_xor_sync(0xffffffffu, c1, o);
        }
        if (tig == 0) {
            int m0 = mt * TM + warpM * 64 + mf * 16 + g;
            g_pho1[(size_t)m0 * KT + lcol] = s0 / (c0 + 1e-6f);
            g_pho1[(size_t)(m0 + 8) * KT + lcol] = s1 / (c1 + 1e-6f);
        }
    }
}

// ---------------------------------------------------------------------------
// Kernel 3: stage-2 gate + masked mean. One warp per (k,l).
// ---------------------------------------------------------------------------
__global__ __launch_bounds__(256) void stage2_kernel(
    const float* __restrict__ fc1w, const float* __restrict__ fc1b,
    const float* __restrict__ fc2w, float* __restrict__ out)
{
    int pair = blockIdx.x * 8 + (threadIdx.x >> 5);
    int lid = threadIdx.x & 31;
    int k = pair / KT, l = pair % KT;

    float w1[CG], b1[CG], w2[CG];
    #pragma unroll
    for (int q = 0; q < CG; q++) { w1[q] = fc1w[q]; b1[q] = fc1b[q]; w2[q] = fc2w[q]; }

    float s = 0.f, cnt = 0.f;
    {
        float v = g_pho1[(size_t)(k * PB + lid) * KT + l];
        cnt += (v != 0.0f) ? 1.0f : 0.0f;
        s = fmaf(gate_fn(v, w1, b1, w2), v, s);
    }
    if (lid < PB - 32) {
        float v = g_pho1[(size_t)(k * PB + 32 + lid) * KT + l];
        cnt += (v != 0.0f) ? 1.0f : 0.0f;
        s = fmaf(gate_fn(v, w1, b1, w2), v, s);
    }
    #pragma unroll
    for (int o = 16; o; o >>= 1) {
        s   += __shfl_down_sync(0xffffffffu, s, o);
        cnt += __shfl_down_sync(0xffffffffu, cnt, o);
    }
    if (lid == 0) out[k * KT + l] = s / (cnt + 1e-6f);
}

// ---------------------------------------------------------------------------
extern "C" void kernel_launch(void* const* d_in, const int* in_sizes, int n_in,
                              void* d_out, int out_size)
{
    const float* enroll = (const float*)d_in[0];
    const float* test   = (const float*)d_in[1];
    const float* fc1w   = (const float*)d_in[2];
    const float* fc1b   = (const float*)d_in[3];
    const float* fc2w   = (const float*)d_in[4];
    float* out = (float*)d_out;

    cudaFuncSetAttribute(gemm_kernel,
                         cudaFuncAttributeMaxDynamicSharedMemorySize, SMEM_BYTES);
    cudaFuncSetAttribute(gemm_kernel,
                         cudaFuncAttributePreferredSharedMemoryCarveout,
                         cudaSharedmemCarveoutMaxShared);

    lut_kernel<<<1, 1024>>>(fc1w, fc1b, fc2w);
    scale_kernel<<<2 * KT, 320>>>(enroll, test);
    scatter_kernel<<<dim3(2 * KT, 4), 320>>>(enroll, test);
    dim3 grid(NMT, NNT);
    gemm_kernel<<<grid, 256, SMEM_BYTES>>>();
    stage2_kernel<<<(KT * KT) / 8, 256>>>(fc1w, fc1b, fc2w, out);
}